// round 5
// baseline (speedup 1.0000x reference)
#include <cuda_runtime.h>

#define BB 2
#define CC 128
#define HH 128
#define WW 256
#define KK 20
#define HW (HH * WW)
#define EPSV 1e-12f

typedef unsigned long long u64;

__device__ float g_invn[BB * HH * CC];  // [b][h][c]
__device__ float g_pnT[CC * KK];        // [c][k] normalized prototypes
__device__ float g_pn2[KK];             // ||pn_k||^2

__device__ __forceinline__ u64 pk2(float lo, float hi) {
    u64 r; asm("mov.b64 %0, {%1,%2};" : "=l"(r) : "f"(lo), "f"(hi)); return r;
}
__device__ __forceinline__ void upk2(u64 v, float& lo, float& hi) {
    asm("mov.b64 {%0,%1}, %2;" : "=f"(lo), "=f"(hi) : "l"(v));
}
__device__ __forceinline__ u64 fma2_(u64 a, u64 b, u64 c) {
    u64 d; asm("fma.rn.f32x2 %0, %1, %2, %3;" : "=l"(d) : "l"(a), "l"(b), "l"(c)); return d;
}
__device__ __forceinline__ u64 mul2_(u64 a, u64 b) {
    u64 d; asm("mul.rn.f32x2 %0, %1, %2;" : "=l"(d) : "l"(a), "l"(b)); return d;
}
__device__ __forceinline__ u64 add2_(u64 a, u64 b) {
    u64 d; asm("add.rn.f32x2 %0, %1, %2;" : "=l"(d) : "l"(a), "l"(b)); return d;
}
__device__ __forceinline__ float wred(float v) {
#pragma unroll
    for (int o = 16; o > 0; o >>= 1) v += __shfl_xor_sync(0xffffffffu, v, o);
    return v;
}
__device__ __forceinline__ float dot4(float4 a) {
    return a.x * a.x + a.y * a.y + a.z * a.z + a.w * a.w;
}

// Kernel 1: blocks 0..127 -> W-norms, one thread per (b,c,h) row, no shuffles.
//           block 128     -> prototype normalization.
__global__ __launch_bounds__(256) void prep_kernel(const float* __restrict__ f,
                                                   const float* __restrict__ p) {
    int tid = threadIdx.x;
    if (blockIdx.x < 128) {
        int r = blockIdx.x * 256 + tid;             // row id = (b*CC + c)*HH + h
        const float4* rp = (const float4*)(f + (size_t)r * WW);
        float s = 0.0f;
#pragma unroll 8
        for (int i = 0; i < WW / 4; i++) s += dot4(rp[i]);
        int h = r & (HH - 1);
        int bc = r >> 7;
        int c = bc & (CC - 1);
        int b = bc >> 7;
        g_invn[(b * HH + h) * CC + c] = 1.0f / fmaxf(sqrtf(s), EPSV);
    } else {
        int w = tid >> 5, lane = tid & 31;
        for (int k = w; k < KK; k += 8) {
            float4 a = ((const float4*)(p + k * CC))[lane];
            float s = wred(dot4(a));
            float inv = 1.0f / fmaxf(sqrtf(s), EPSV);
            int cb = lane * 4;
            g_pnT[(cb + 0) * KK + k] = a.x * inv;
            g_pnT[(cb + 1) * KK + k] = a.y * inv;
            g_pnT[(cb + 2) * KK + k] = a.z * inv;
            g_pnT[(cb + 3) * KK + k] = a.w * inv;
            if (lane == 0) g_pn2[k] = s * inv * inv;
        }
    }
}

// 16-c chunk of the dot loop; padded prototype rows -> 2x LDS.128 + 1x LDS.64.
template <bool DO_S2>
__device__ __forceinline__ void chunk16(const float4* __restrict__ fp, int ccb,
                                        const u64* __restrict__ pb,
                                        const u64* __restrict__ r2b,
                                        u64 acc[2][5], u64 s2[2]) {
#pragma unroll 4
    for (int t = 0; t < 16; t++) {
        int cc = ccb + t;
        float4 xv = fp[(size_t)cc * (HW / 4)];
        u64 x0 = pk2(xv.x, xv.y);
        u64 x1 = pk2(xv.z, xv.w);
        const u64* pr = pb + cc * 24;
        ulonglong2 q0 = *(const ulonglong2*)(pr);
        ulonglong2 q1 = *(const ulonglong2*)(pr + 2);
        u64 p4 = pr[4];
        acc[0][0] = fma2_(x0, q0.x, acc[0][0]);
        acc[1][0] = fma2_(x1, q0.x, acc[1][0]);
        acc[0][1] = fma2_(x0, q0.y, acc[0][1]);
        acc[1][1] = fma2_(x1, q0.y, acc[1][1]);
        acc[0][2] = fma2_(x0, q1.x, acc[0][2]);
        acc[1][2] = fma2_(x1, q1.x, acc[1][2]);
        acc[0][3] = fma2_(x0, q1.y, acc[0][3]);
        acc[1][3] = fma2_(x1, q1.y, acc[1][3]);
        acc[0][4] = fma2_(x0, p4, acc[0][4]);
        acc[1][4] = fma2_(x1, p4, acc[1][4]);
        if (DO_S2) {
            u64 r2 = r2b[cc];
            s2[0] = fma2_(mul2_(x0, r2), x0, s2[0]);
            s2[1] = fma2_(mul2_(x1, r2), x1, s2[1]);
        }
    }
}

// Kernel 2: main. Block = (b, h, w-half): 512 blocks x 256 threads, one wave.
// tid: pxg bits0-4 (32 groups x 4 px), kg bits5-6 (4 x 5 k), ch bit7 (c-half).
__global__ __launch_bounds__(256, 4) void main_kernel(const float* __restrict__ f,
                                                      const float* __restrict__ ds,
                                                      float* __restrict__ out) {
    __shared__ u64 s_pn[CC * 24];   // padded folded protos; aliased for reductions after
    __shared__ u64 s_r2[CC];
    __shared__ float s_inv[CC];
    __shared__ float s_pn2[KK];

    int tid = threadIdx.x;
    int wh = blockIdx.x & 1;
    int h = (blockIdx.x >> 1) & (HH - 1);
    int b = blockIdx.x >> 8;
    const float* fbh = f + (size_t)b * CC * HW + (size_t)h * WW;

    // Load inv-norms + build folded prototype table
    if (tid < CC) {
        float r = g_invn[(size_t)(b * HH + h) * CC + tid];
        s_inv[tid] = r;
        s_r2[tid] = pk2(r * r, r * r);
    }
    if (tid < KK) s_pn2[tid] = g_pn2[tid];
    __syncthreads();
    for (int i = tid; i < CC * KK; i += 256) {
        int c = i / KK, k = i - c * KK;
        int kg_ = k / 5, j = k - kg_ * 5;
        float val = __ldg(g_pnT + i) * s_inv[c];
        s_pn[(c * 4 + kg_) * 6 + j] = pk2(val, val);
    }
    __syncthreads();

    int pxg = tid & 31;
    int kg = (tid >> 5) & 3;
    int ch = tid >> 7;
    int c0 = ch * 64;

    const float4* fp = (const float4*)fbh + (size_t)c0 * (HW / 4) + wh * 32 + pxg;
    const u64* pb = s_pn + (size_t)(c0 * 4 + kg) * 6;
    const u64* r2b = s_r2 + c0;

    u64 acc[2][5];
#pragma unroll
    for (int j = 0; j < 5; j++) { acc[0][j] = 0ull; acc[1][j] = 0ull; }
    u64 s2[2] = {0ull, 0ull};

#pragma unroll
    for (int seg = 0; seg < 4; seg++) {
        if (seg == kg) chunk16<true>(fp, seg * 16, pb, r2b, acc, s2);
        else           chunk16<false>(fp, seg * 16, pb, r2b, acc, s2);
    }

    // Reductions (alias dead s_pn)
    __syncthreads();
    u64* s_red = s_pn;              // ch1 dot partials [128][10]
    u64* s_s2p = s_pn + 1280;       // s2 partials [8][64]
    s_s2p[(size_t)(ch * 4 + kg) * 64 + 2 * pxg]     = s2[0];
    s_s2p[(size_t)(ch * 4 + kg) * 64 + 2 * pxg + 1] = s2[1];
    if (ch == 1) {
        u64* r = s_red + (size_t)(tid & 127) * 10;
#pragma unroll
        for (int i = 0; i < 2; i++)
#pragma unroll
            for (int j = 0; j < 5; j++) r[i * 5 + j] = acc[i][j];
    }
    __syncthreads();

    if (ch == 0) {
        const u64* r = s_red + (size_t)tid * 10;
#pragma unroll
        for (int i = 0; i < 2; i++)
#pragma unroll
            for (int j = 0; j < 5; j++) acc[i][j] = add2_(acc[i][j], r[i * 5 + j]);

        u64 t0 = 0ull, t1 = 0ull;
#pragma unroll
        for (int g = 0; g < 8; g++) {
            t0 = add2_(t0, s_s2p[g * 64 + 2 * pxg]);
            t1 = add2_(t1, s_s2p[g * 64 + 2 * pxg + 1]);
        }
        float n0, n1, n2, n3;
        upk2(t0, n0, n1);
        upk2(t1, n2, n3);

        float scale = fabsf(ds[0]);
        float* ob = out + (size_t)b * KK * HW + (size_t)h * WW + wh * 128 + 4 * pxg;
#pragma unroll
        for (int j = 0; j < 5; j++) {
            int k = kg * 5 + j;
            float q = s_pn2[k];
            float d0, d1, d2, d3;
            upk2(acc[0][j], d0, d1);
            upk2(acc[1][j], d2, d3);
            float4 o;
            o.x = -scale * sqrtf(fmaxf(n0 + q - 2.0f * d0, 0.0f));
            o.y = -scale * sqrtf(fmaxf(n1 + q - 2.0f * d1, 0.0f));
            o.z = -scale * sqrtf(fmaxf(n2 + q - 2.0f * d2, 0.0f));
            o.w = -scale * sqrtf(fmaxf(n3 + q - 2.0f * d3, 0.0f));
            *(float4*)(ob + (size_t)k * HW) = o;
        }
    }
}

extern "C" void kernel_launch(void* const* d_in, const int* in_sizes, int n_in,
                              void* d_out, int out_size) {
    const float* features   = (const float*)d_in[0];
    const float* prototypes = (const float*)d_in[1];
    const float* dscale     = (const float*)d_in[2];
    float* out = (float*)d_out;

    prep_kernel<<<129, 256>>>(features, prototypes);
    main_kernel<<<BB * HH * 2, 256>>>(features, dscale, out);
}

// round 6
// speedup vs baseline: 1.3561x; 1.3561x over previous
#include <cuda_runtime.h>

#define BB 2
#define CC 128
#define HH 128
#define WW 256
#define KK 20
#define HW (HH * WW)
#define EPSV 1e-12f

typedef unsigned long long u64;

__device__ __forceinline__ u64 pk2(float lo, float hi) {
    u64 r; asm("mov.b64 %0, {%1,%2};" : "=l"(r) : "f"(lo), "f"(hi)); return r;
}
__device__ __forceinline__ void upk2(u64 v, float& lo, float& hi) {
    asm("mov.b64 {%0,%1}, %2;" : "=f"(lo), "=f"(hi) : "l"(v));
}
__device__ __forceinline__ u64 fma2_(u64 a, u64 b, u64 c) {
    u64 d; asm("fma.rn.f32x2 %0, %1, %2, %3;" : "=l"(d) : "l"(a), "l"(b), "l"(c)); return d;
}
__device__ __forceinline__ u64 mul2_(u64 a, u64 b) {
    u64 d; asm("mul.rn.f32x2 %0, %1, %2;" : "=l"(d) : "l"(a), "l"(b)); return d;
}
__device__ __forceinline__ u64 add2_(u64 a, u64 b) {
    u64 d; asm("add.rn.f32x2 %0, %1, %2;" : "=l"(d) : "l"(a), "l"(b)); return d;
}
__device__ __forceinline__ float wred(float v) {
#pragma unroll
    for (int o = 16; o > 0; o >>= 1) v += __shfl_xor_sync(0xffffffffu, v, o);
    return v;
}
__device__ __forceinline__ float dot4(float4 a) {
    return a.x * a.x + a.y * a.y + a.z * a.z + a.w * a.w;
}

// 16-c chunk; padded prototype rows -> 2x LDS.128 + 1x LDS.64 per c.
// DO_S2 chunks also accumulate ||fn||^2 (each (ch,kg) group covers its own 16 c).
template <bool DO_S2>
__device__ __forceinline__ void chunk16(const float4* __restrict__ fp, int ccb,
                                        const u64* __restrict__ pb,     // s_pn + (c0*4+kg)*6
                                        const u64* __restrict__ r2b,    // s_r2 + c0
                                        u64 acc[2][5], u64 s2[2]) {
#pragma unroll 4
    for (int t = 0; t < 16; t++) {
        int cc = ccb + t;
        float4 xv = fp[(size_t)cc * (HW / 4)];
        u64 x0 = pk2(xv.x, xv.y);
        u64 x1 = pk2(xv.z, xv.w);
        const u64* pr = pb + cc * 24;
        ulonglong2 q0 = *(const ulonglong2*)(pr);
        ulonglong2 q1 = *(const ulonglong2*)(pr + 2);
        u64 p4 = pr[4];
        acc[0][0] = fma2_(x0, q0.x, acc[0][0]);
        acc[1][0] = fma2_(x1, q0.x, acc[1][0]);
        acc[0][1] = fma2_(x0, q0.y, acc[0][1]);
        acc[1][1] = fma2_(x1, q0.y, acc[1][1]);
        acc[0][2] = fma2_(x0, q1.x, acc[0][2]);
        acc[1][2] = fma2_(x1, q1.x, acc[1][2]);
        acc[0][3] = fma2_(x0, q1.y, acc[0][3]);
        acc[1][3] = fma2_(x1, q1.y, acc[1][3]);
        acc[0][4] = fma2_(x0, p4, acc[0][4]);
        acc[1][4] = fma2_(x1, p4, acc[1][4]);
        if (DO_S2) {
            u64 r2 = r2b[cc];
            s2[0] = fma2_(mul2_(x0, r2), x0, s2[0]);
            s2[1] = fma2_(mul2_(x1, r2), x1, s2[1]);
        }
    }
}

// Single fused kernel (round-3 structure). Block = (b,h), 512 threads.
// tid: pxg bits0-5 (64 groups x 4 px), kg bits6-7 (4 x 5 k), ch bit8 (c-half).
__global__ __launch_bounds__(512, 2) void iso_kernel(const float* __restrict__ f,
                                                     const float* __restrict__ p,
                                                     const float* __restrict__ ds,
                                                     float* __restrict__ out) {
    __shared__ u64 s_pn[CC * 24];    // padded folded protos (24 KB); aliased for ch1 partials
    __shared__ u64 s_s2p[8 * 128];   // s2 partials per (ch*4+kg) group (8 KB)
    __shared__ u64 s_r2[CC];         // inv_c^2 dup-packed
    __shared__ float s_inv[CC];
    __shared__ float s_pinv[KK];
    __shared__ float s_pn2[KK];

    int tid = threadIdx.x;
    int w = tid >> 5, lane = tid & 31;
    int b = blockIdx.x / HH, h = blockIdx.x % HH;
    const float* fbh = f + (size_t)b * CC * HW + (size_t)h * WW;

    // ---- Pass 1a: W-norms; warp w handles c = w + 16j (8 c/warp, batches of 4 rows)
#pragma unroll
    for (int jb = 0; jb < 2; jb++) {
        float4 v[8];
        int cbase = w + jb * 64;
#pragma unroll
        for (int j = 0; j < 4; j++) {
            const float4* r4 = (const float4*)(fbh + (size_t)(cbase + 16 * j) * HW);
            v[2 * j]     = r4[lane];
            v[2 * j + 1] = r4[lane + 32];
        }
#pragma unroll
        for (int j = 0; j < 4; j++) {
            float s = wred(dot4(v[2 * j]) + dot4(v[2 * j + 1]));
            if (lane == 0) {
                int c = cbase + 16 * j;
                float r = 1.0f / fmaxf(sqrtf(s), EPSV);
                s_inv[c] = r;
                s_r2[c] = pk2(r * r, r * r);
            }
        }
    }
    // ---- Pass 1b: prototype norms
    for (int k = w; k < KK; k += 16) {
        float4 a = ((const float4*)(p + k * CC))[lane];
        float s = wred(dot4(a));
        if (lane == 0) {
            float inv = 1.0f / fmaxf(sqrtf(s), EPSV);
            s_pinv[k] = inv;
            s_pn2[k] = s * inv * inv;
        }
    }
    __syncthreads();

    // ---- Folded prototype table, padded layout: s_pn[(c*4+kg)*6+j]
    for (int i = tid; i < CC * KK; i += 512) {
        int c = i / KK, k = i - c * KK;
        int kg_ = k / 5, j = k - kg_ * 5;
        float val = __ldg(p + k * CC + c) * s_pinv[k] * s_inv[c];
        s_pn[(c * 4 + kg_) * 6 + j] = pk2(val, val);
    }
    __syncthreads();

    // ---- Main dot loop
    int pxg = tid & 63;
    int kg = (tid >> 6) & 3;
    int ch = tid >> 8;
    int c0 = ch * 64;

    const float4* fp = (const float4*)fbh + (size_t)c0 * (HW / 4) + pxg;
    const u64* pb = s_pn + (size_t)(c0 * 4 + kg) * 6;
    const u64* r2b = s_r2 + c0;

    u64 acc[2][5];
#pragma unroll
    for (int j = 0; j < 5; j++) { acc[0][j] = 0ull; acc[1][j] = 0ull; }
    u64 s2[2] = {0ull, 0ull};

#pragma unroll
    for (int seg = 0; seg < 4; seg++) {
        if (seg == kg) chunk16<true>(fp, seg * 16, pb, r2b, acc, s2);
        else           chunk16<false>(fp, seg * 16, pb, r2b, acc, s2);
    }

    // ---- Reductions (alias dead s_pn for ch1 dot partials)
    s_s2p[(size_t)(ch * 4 + kg) * 128 + 2 * pxg]     = s2[0];
    s_s2p[(size_t)(ch * 4 + kg) * 128 + 2 * pxg + 1] = s2[1];
    __syncthreads();            // also protects s_pn reuse below
    u64* s_red = s_pn;          // [256 threads][10]
    if (ch == 1) {
        u64* r = s_red + (size_t)(tid & 255) * 10;
#pragma unroll
        for (int i = 0; i < 2; i++)
#pragma unroll
            for (int j = 0; j < 5; j++) r[i * 5 + j] = acc[i][j];
    }
    __syncthreads();

    if (ch == 0) {
        const u64* r = s_red + (size_t)tid * 10;
#pragma unroll
        for (int i = 0; i < 2; i++)
#pragma unroll
            for (int j = 0; j < 5; j++) acc[i][j] = add2_(acc[i][j], r[i * 5 + j]);

        u64 t0 = 0ull, t1 = 0ull;
#pragma unroll
        for (int g = 0; g < 8; g++) {
            t0 = add2_(t0, s_s2p[g * 128 + 2 * pxg]);
            t1 = add2_(t1, s_s2p[g * 128 + 2 * pxg + 1]);
        }
        float n0, n1, n2, n3;
        upk2(t0, n0, n1);
        upk2(t1, n2, n3);

        float scale = fabsf(ds[0]);
        float* ob = out + (size_t)b * KK * HW + (size_t)h * WW + 4 * pxg;
#pragma unroll
        for (int j = 0; j < 5; j++) {
            int k = kg * 5 + j;
            float q = s_pn2[k];
            float d0, d1, d2, d3;
            upk2(acc[0][j], d0, d1);
            upk2(acc[1][j], d2, d3);
            float4 o;
            o.x = -scale * sqrtf(fmaxf(n0 + q - 2.0f * d0, 0.0f));
            o.y = -scale * sqrtf(fmaxf(n1 + q - 2.0f * d1, 0.0f));
            o.z = -scale * sqrtf(fmaxf(n2 + q - 2.0f * d2, 0.0f));
            o.w = -scale * sqrtf(fmaxf(n3 + q - 2.0f * d3, 0.0f));
            *(float4*)(ob + (size_t)k * HW) = o;
        }
    }
}

extern "C" void kernel_launch(void* const* d_in, const int* in_sizes, int n_in,
                              void* d_out, int out_size) {
    const float* features   = (const float*)d_in[0];
    const float* prototypes = (const float*)d_in[1];
    const float* dscale     = (const float*)d_in[2];
    float* out = (float*)d_out;

    iso_kernel<<<BB * HH, 512>>>(features, prototypes, dscale, out);
}